// round 10
// baseline (speedup 1.0000x reference)
#include <cuda_runtime.h>
#include <math.h>

// x[16,64,256,256] f32, w[1,2,3,3] f32
#define B_   16
#define C_   64
#define H_   256
#define W_   256
#define TH   8
#define TW   32
#define HH_  (TH + 2)          // 10
#define HW_  (TW + 2)          // 34
#define NHALO (HH_ * HW_)      // 340
#define NINT  (TH * TW)        // 256
#define NRING (NHALO - NINT)   // 84 ring pixels
#define NT    320
#define CH2   (C_ / 2)         // 32 channels per half
#define HWIMG (H_ * W_)
#define CHW   (C_ * HWIMG)
#define TILES_PER_IMG 256      // (256/8)*(256/32) = 32*8
#define NTILES (B_ * TILES_PER_IMG)   // 4096
#define GRID  912              // 152 SMs * 6 blocks: one wave, persistent

__global__ void __launch_bounds__(NT, 6)
spatial_attention_kernel(const float* __restrict__ x,
                         const float* __restrict__ w,
                         float* __restrict__ out) {
    // Phase-1 partials
    __shared__ float s_ps[2 * NINT];
    __shared__ float s_pm[2 * NINT];
    __shared__ float s_rs[2 * NRING];
    __shared__ float s_rm[2 * NRING];
    // Pooled maps + attn
    __shared__ float s_max[NHALO];
    __shared__ float s_avg[NHALO];
    __shared__ float s_attn[NINT];
    __shared__ float s_w[18];

    const int tid = threadIdx.x;
    if (tid < 18) s_w[tid] = w[tid];

    // Thread roles (tile-independent)
    const int ig  = tid & 63;            // interior float4 group
    const int ih  = tid >> 6;            // interior channel-half (valid if tid<128)
    const int ipy = ig >> 3;
    const int ipx = (ig & 7) * 4;

    int rh = 0, rr = 0, rhy = 0, rhx = 0;
    const bool is_ring = (tid >= 128) && (tid < 128 + 2 * NRING);
    if (is_ring) {
        const int j = tid - 128;
        rh = (j >= NRING);
        rr = j - rh * NRING;
        if (rr < 34)      { rhy = 0;       rhx = rr; }
        else if (rr < 68) { rhy = HH_ - 1; rhx = rr - 34; }
        else              { const int k = rr - 68; rhy = 1 + (k >> 1); rhx = (k & 1) ? (HW_ - 1) : 0; }
    }

    // Phase-3 role
    const int c0 = tid >> 6;             // 0..4
    const float* a_ptr = &s_attn[ipy * TW + ipx];

    for (int t = blockIdx.x; t < NTILES; t += GRID) {
        const int b   = t >> 8;
        const int rem = t & 255;
        const int y0  = (rem >> 3) * TH;
        const int x0  = (rem & 7) * TW;
        const float* __restrict__ xb = x + (size_t)b * CHW;

        // ---- Phase 1: vectorized pooling (overlaps prev tile's stores) --
        if (tid < 128) {
            const float4* __restrict__ p = reinterpret_cast<const float4*>(
                xb + (size_t)(ih * CH2) * HWIMG + (size_t)(y0 + ipy) * W_ + (x0 + ipx));
            const int cstride = HWIMG / 4;
            float4 s = make_float4(0.f, 0.f, 0.f, 0.f);
            float4 m = make_float4(-1e30f, -1e30f, -1e30f, -1e30f);
#pragma unroll 8
            for (int c = 0; c < CH2; c++) {
                const float4 v = __ldg(p + (size_t)c * cstride);
                s.x += v.x; s.y += v.y; s.z += v.z; s.w += v.w;
                m.x = fmaxf(m.x, v.x); m.y = fmaxf(m.y, v.y);
                m.z = fmaxf(m.z, v.z); m.w = fmaxf(m.w, v.w);
            }
            *reinterpret_cast<float4*>(&s_ps[ih * NINT + ig * 4]) = s;
            *reinterpret_cast<float4*>(&s_pm[ih * NINT + ig * 4]) = m;
        } else if (is_ring) {
            const int Y = y0 - 1 + rhy;
            const int X = x0 - 1 + rhx;
            const bool inb = (Y >= 0) & (Y < H_) & (X >= 0) & (X < W_);
            float s = 0.0f, m = -1e30f;
            if (inb) {
                const float* __restrict__ p =
                    xb + (size_t)(rh * CH2) * HWIMG + (size_t)Y * W_ + X;
#pragma unroll 8
                for (int c = 0; c < CH2; c++) {
                    const float v = __ldg(p + (size_t)c * HWIMG);
                    s += v;
                    m = fmaxf(m, v);
                }
            }
            s_rs[rh * NRING + rr] = inb ? s : 0.0f;
            s_rm[rh * NRING + rr] = inb ? m : 0.0f;
        }
        __syncthreads();

        // ---- Combine partials -> pooled maps ----------------------------
        for (int q = tid; q < NHALO; q += NT) {
            const int hy = q / HW_;
            const int hx = q - hy * HW_;
            float sum, mx;
            if (hy >= 1 && hy <= TH && hx >= 1 && hx <= TW) {
                const int e = (hy - 1) * TW + (hx - 1);
                sum = s_ps[e] + s_ps[NINT + e];
                mx  = fmaxf(s_pm[e], s_pm[NINT + e]);
            } else {
                int r;
                if (hy == 0)            r = hx;
                else if (hy == HH_ - 1) r = 34 + hx;
                else                    r = 68 + (hy - 1) * 2 + (hx != 0);
                sum = s_rs[r] + s_rs[NRING + r];
                mx  = fmaxf(s_rm[r], s_rm[NRING + r]);
            }
            s_avg[q] = sum * (1.0f / C_);
            s_max[q] = mx;
        }
        __syncthreads();

        // ---- Conv 3x3 (concat [max, avg]) + sigmoid ---------------------
        if (tid < NINT) {
            const int y  = tid >> 5;
            const int xq = tid & 31;
            float acc = 0.0f;
#pragma unroll
            for (int dy = 0; dy < 3; dy++) {
#pragma unroll
                for (int dx = 0; dx < 3; dx++) {
                    const int hi = (y + dy) * HW_ + (xq + dx);
                    acc += s_w[dy * 3 + dx]     * s_max[hi];
                    acc += s_w[9 + dy * 3 + dx] * s_avg[hi];
                }
            }
            s_attn[tid] = 1.0f / (1.0f + expf(-acc));
        }
        __syncthreads();

        // ---- Phase 3: multiply + streamed stores (no trailing barrier) --
        const float4 a = *reinterpret_cast<const float4*>(a_ptr);
        const size_t base = (size_t)(y0 + ipy) * W_ + (x0 + ipx);
        float* __restrict__ ob = out + (size_t)b * CHW;

        for (int c = c0; c < C_; c += 5) {
            float4 v = __ldg(reinterpret_cast<const float4*>(xb + (size_t)c * HWIMG + base));
            v.x *= a.x; v.y *= a.y; v.z *= a.z; v.w *= a.w;
            __stcs(reinterpret_cast<float4*>(ob + (size_t)c * HWIMG + base), v);
        }
        // next tile's phase 1 overlaps these stores
    }
}

extern "C" void kernel_launch(void* const* d_in, const int* in_sizes, int n_in,
                              void* d_out, int out_size) {
    const float* x = (const float*)d_in[0];
    const float* w = (const float*)d_in[1];
    float* out     = (float*)d_out;

    spatial_attention_kernel<<<GRID, NT>>>(x, w, out);
}